// round 14
// baseline (speedup 1.0000x reference)
#include <cuda_runtime.h>
#include <cuda_bf16.h>

// OccupancyGridForestAS: 4.19M points, 8x8x8 block lookup -> 64 trees of 64^3 voxels.
//
// inputs (metadata order):
//   d_in[0]: pts            float32 [N_PTS, 3]
//   d_in[1]: occ_val_grid   float32 [64, 64, 64, 64]
//   d_in[2]: block_lookup   int32   [8, 8, 8]
// output: float32 [N_PTS]
//
// R14: champion R13 body/geometry, single variable changed: pts loads use
// DEFAULT caching (not __ldcs/evict-first). Steady-state hot set = pts 48MB
// + gather sector set 16MB = 64MB < 126MB L2, so across graph replays both
// read sets can stay L2-resident; DRAM steady traffic ~= 16MB output only.
// Output stays __stcs (evict-first write-back -- NOT R6's __stwt, the
// suspected poison). Gathers stay __ldcg (L1 bypass, default L2 eviction).

#define RES   64
#define LDIM  8
#define NTHREADS 256
#define NBLOCKS  2048

__global__ void __launch_bounds__(NTHREADS)
occ_forest_kernel(const float4* __restrict__ pts4,
                  const float*  __restrict__ occ,
                  const int*    __restrict__ lut,
                  float4*       __restrict__ out4,
                  int nc)                      // number of 4-point chunks
{
    __shared__ int s_lut[LDIM * LDIM * LDIM];  // 512 ints = 2KB
    {
        int tid = threadIdx.x;
        s_lut[tid]       = lut[tid];
        s_lut[tid + 256] = lut[tid + 256];
    }
    __syncthreads();

    const int stride = gridDim.x * blockDim.x;

#pragma unroll 1
    for (int t = blockIdx.x * blockDim.x + threadIdx.x; t < nc; t += stride) {
        // 4 points = 12 floats = 3 float4 (coalesced; DEFAULT eviction so the
        // pts stream can persist in L2 across graph replays)
        float4 a = __ldg(&pts4[3 * t + 0]);
        float4 b = __ldg(&pts4[3 * t + 1]);
        float4 c = __ldg(&pts4[3 * t + 2]);

        float px[4] = {a.x, a.w, b.z, c.y};
        float py[4] = {a.y, b.x, b.w, c.z};
        float pz[4] = {a.z, b.y, c.x, c.w};

        int  idx[4];
        bool valid[4];

        // Phase 1: index math for all 4 points (no cross-point dependencies)
#pragma unroll
        for (int i = 0; i < 4; i++) {
            float x = px[i], y = py[i], z = pz[i];

            int bx = (int)floorf(x);
            int by = (int)floorf(y);
            int bz = (int)floorf(z);

            bool in_dom = (bx >= 0) & (bx < LDIM) &
                          (by >= 0) & (by < LDIM) &
                          (bz >= 0) & (bz < LDIM);

            int cx = min(max(bx, 0), LDIM - 1);
            int cy = min(max(by, 0), LDIM - 1);
            int cz = min(max(bz, 0), LDIM - 1);

            int bidx = s_lut[cx * (LDIM * LDIM) + cy * LDIM + cz];
            valid[i] = in_dom && (bidx >= 0);

            // Bit-exact reference float sequence:
            //   block_x = 2*(p - bcs) - 1 ; vox = floor((block_x*0.5+0.5)*RES)
            // valid => x-cx in [0,1) => vox in [0,63]; clamps elided
            // (invalid points never issue the load).
            float bxf = 2.0f * (x - (float)cx) - 1.0f;
            float byf = 2.0f * (y - (float)cy) - 1.0f;
            float bzf = 2.0f * (z - (float)cz) - 1.0f;

            int vx = (int)floorf((bxf * 0.5f + 0.5f) * (float)RES);
            int vy = (int)floorf((byf * 0.5f + 0.5f) * (float)RES);
            int vz = (int)floorf((bzf * 0.5f + 0.5f) * (float)RES);

            idx[i] = bidx * (RES * RES * RES) + vx * (RES * RES) + vy * RES + vz;
        }

        // Phase 2: 4 independent predicated gathers (L2-only path; the hot
        // 16MB sector set persists in L2 across replays)
        float r[4];
#pragma unroll
        for (int i = 0; i < 4; i++)
            r[i] = valid[i] ? __ldcg(&occ[idx[i]]) : 0.0f;

        float4 o;
        o.x = r[0]; o.y = r[1]; o.z = r[2]; o.w = r[3];
        __stcs(&out4[t], o);   // evict-first write-back (NOT write-through)
    }
}

extern "C" void kernel_launch(void* const* d_in, const int* in_sizes, int n_in,
                              void* d_out, int out_size)
{
    const float4* pts4 = (const float4*)d_in[0];
    const float*  occ  = (const float*)d_in[1];
    const int*    lut  = (const int*)d_in[2];
    float4*       out  = (float4*)d_out;

    int n_pts = in_sizes[0] / 3;       // 4,194,304
    int nc    = n_pts / 4;             // 1,048,576 4-point chunks

    // 2048 blocks x 256 threads x 2 iterations == nc exactly.
    occ_forest_kernel<<<NBLOCKS, NTHREADS>>>(pts4, occ, lut, out, nc);
}

// round 15
// speedup vs baseline: 1.1382x; 1.1382x over previous
#include <cuda_runtime.h>
#include <cuda_bf16.h>
#include <cstdint>

// OccupancyGridForestAS: 4.19M points, 8x8x8 block lookup -> 64 trees of 64^3 voxels.
//
// inputs (metadata order):
//   d_in[0]: pts            float32 [N_PTS, 3]
//   d_in[1]: occ_val_grid   float32 [64, 64, 64, 64]
//   d_in[2]: block_lookup   int32   [8, 8, 8]
// output: float32 [N_PTS]
//
// R15: champion R13, single variable changed: the occ-grid gathers carry an
// L2::evict_last cache policy (createpolicy + ld.global.nc.L2::cache_hint).
// The ~16MB hot gather-sector set is re-touched identically every graph
// replay; R14 proved it is what persists in L2 (and that pts pollution of it
// costs 2us). Pinning it at high replacement priority should push gather L2
// hit rate to ~100% in steady state.
// Everything else identical to R13: 4 pts/iter, __ldcs pts (evict-first),
// __stcs out, smem lut, clamp-free vox, 2048 blocks x 256 thr x 2 iters.

#define RES   64
#define LDIM  8
#define NTHREADS 256
#define NBLOCKS  2048

__device__ __forceinline__ float ldg_evict_last(const float* p, uint64_t pol) {
    float v;
    asm volatile("ld.global.nc.L2::cache_hint.f32 %0, [%1], %2;"
                 : "=f"(v) : "l"(p), "l"(pol));
    return v;
}

__global__ void __launch_bounds__(NTHREADS)
occ_forest_kernel(const float4* __restrict__ pts4,
                  const float*  __restrict__ occ,
                  const int*    __restrict__ lut,
                  float4*       __restrict__ out4,
                  int nc)                      // number of 4-point chunks
{
    __shared__ int s_lut[LDIM * LDIM * LDIM];  // 512 ints = 2KB
    {
        int tid = threadIdx.x;
        s_lut[tid]       = lut[tid];
        s_lut[tid + 256] = lut[tid + 256];
    }
    __syncthreads();

    // High-priority L2 residency for the hot gather-sector set.
    uint64_t pol;
    asm("createpolicy.fractional.L2::evict_last.b64 %0, 1.0;" : "=l"(pol));

    const int stride = gridDim.x * blockDim.x;

#pragma unroll 1
    for (int t = blockIdx.x * blockDim.x + threadIdx.x; t < nc; t += stride) {
        // 4 points = 12 floats = 3 float4 (coalesced, evict-first in L2)
        float4 a = __ldcs(&pts4[3 * t + 0]);
        float4 b = __ldcs(&pts4[3 * t + 1]);
        float4 c = __ldcs(&pts4[3 * t + 2]);

        float px[4] = {a.x, a.w, b.z, c.y};
        float py[4] = {a.y, b.x, b.w, c.z};
        float pz[4] = {a.z, b.y, c.x, c.w};

        int  idx[4];
        bool valid[4];

        // Phase 1: index math for all 4 points (no cross-point dependencies)
#pragma unroll
        for (int i = 0; i < 4; i++) {
            float x = px[i], y = py[i], z = pz[i];

            int bx = (int)floorf(x);
            int by = (int)floorf(y);
            int bz = (int)floorf(z);

            bool in_dom = (bx >= 0) & (bx < LDIM) &
                          (by >= 0) & (by < LDIM) &
                          (bz >= 0) & (bz < LDIM);

            int cx = min(max(bx, 0), LDIM - 1);
            int cy = min(max(by, 0), LDIM - 1);
            int cz = min(max(bz, 0), LDIM - 1);

            int bidx = s_lut[cx * (LDIM * LDIM) + cy * LDIM + cz];
            valid[i] = in_dom && (bidx >= 0);

            // Bit-exact reference float sequence:
            //   block_x = 2*(p - bcs) - 1 ; vox = floor((block_x*0.5+0.5)*RES)
            // valid => x-cx in [0,1) => vox in [0,63]; clamps elided
            // (invalid points never issue the load).
            float bxf = 2.0f * (x - (float)cx) - 1.0f;
            float byf = 2.0f * (y - (float)cy) - 1.0f;
            float bzf = 2.0f * (z - (float)cz) - 1.0f;

            int vx = (int)floorf((bxf * 0.5f + 0.5f) * (float)RES);
            int vy = (int)floorf((byf * 0.5f + 0.5f) * (float)RES);
            int vz = (int)floorf((bzf * 0.5f + 0.5f) * (float)RES);

            idx[i] = bidx * (RES * RES * RES) + vx * (RES * RES) + vy * RES + vz;
        }

        // Phase 2: 4 independent predicated gathers, pinned evict_last in L2
        float r[4];
#pragma unroll
        for (int i = 0; i < 4; i++)
            r[i] = valid[i] ? ldg_evict_last(&occ[idx[i]], pol) : 0.0f;

        float4 o;
        o.x = r[0]; o.y = r[1]; o.z = r[2]; o.w = r[3];
        __stcs(&out4[t], o);
    }
}

extern "C" void kernel_launch(void* const* d_in, const int* in_sizes, int n_in,
                              void* d_out, int out_size)
{
    const float4* pts4 = (const float4*)d_in[0];
    const float*  occ  = (const float*)d_in[1];
    const int*    lut  = (const int*)d_in[2];
    float4*       out  = (float4*)d_out;

    int n_pts = in_sizes[0] / 3;       // 4,194,304
    int nc    = n_pts / 4;             // 1,048,576 4-point chunks

    // 2048 blocks x 256 threads x 2 iterations == nc exactly.
    occ_forest_kernel<<<NBLOCKS, NTHREADS>>>(pts4, occ, lut, out, nc);
}